// round 14
// baseline (speedup 1.0000x reference)
#include <cuda_runtime.h>
#include <math.h>

#define BATCH   8
#define NA      262144
#define KSEL    5000
#define KPAD    5120
#define SORTN   8192
#define NBUCKET 4096
#define NOUT    1000
#define NEGV    (-1000000000.0f)
#define NTHR    1024
#define NPART   32

// ---------------- device-global scratch (no allocations allowed) ----------------
__device__ int                g_histpart[NPART][BATCH][NBUCKET];
__device__ int                g_thr[BATCH];
__device__ int                g_candcnt[BATCH];
__device__ unsigned long long g_candkey[BATCH][SORTN];

// ---------------- helpers ----------------
static __device__ __forceinline__ unsigned orderable(float f) {
    unsigned u = __float_as_uint(f);
    return (u & 0x80000000u) ? ~u : (u | 0x80000000u);
}
static __device__ __forceinline__ float fromOrderable(unsigned k) {
    return __uint_as_float((k & 0x80000000u) ? (k ^ 0x80000000u) : ~k);
}
static __device__ __forceinline__ int bucketOf(float s) {
    int b = (int)(s * 4096.0f);
    b = b < 0 ? 0 : b;
    return b > (NBUCKET - 1) ? (NBUCKET - 1) : b;
}
static __device__ __forceinline__ unsigned part1by1(unsigned v) {
    v &= 0x0000FFFFu;
    v = (v | (v << 8)) & 0x00FF00FFu;
    v = (v | (v << 4)) & 0x0F0F0F0Fu;
    v = (v | (v << 2)) & 0x33333333u;
    v = (v | (v << 1)) & 0x55555555u;
    return v;
}

// Bit-exact replica of XLA:CPU's f32 exp (GenerateVF32Exp): Cephes-style
// Horner with UNFUSED mul+add. Inputs in [-4.14, 4.14]; clamp omitted.
static __device__ __forceinline__ float xla_expf(float x) {
    const float LOG2EF = 1.44269504088896341f;
    const float C1 = 0.693359375f;
    const float C2 = -2.12194440e-4f;
    const float p0 = 1.9875691500E-4f;
    const float p1 = 1.3981999507E-3f;
    const float p2 = 8.3334519073E-3f;
    const float p3 = 4.1665795894E-2f;
    const float p4 = 1.6666665459E-1f;
    const float p5 = 5.0000001201E-1f;
    float fx = floorf(__fadd_rn(0.5f, __fmul_rn(x, LOG2EF)));
    float tmp = __fmul_rn(C1, fx);
    float z0  = __fmul_rn(C2, fx);
    float r = __fsub_rn(x, tmp);
    r = __fsub_rn(r, z0);
    float zz = __fmul_rn(r, r);
    float y;
    y = __fadd_rn(p1, __fmul_rn(r, p0));
    y = __fadd_rn(p2, __fmul_rn(y, r));
    y = __fadd_rn(p3, __fmul_rn(y, r));
    y = __fadd_rn(p4, __fmul_rn(y, r));
    y = __fadd_rn(p5, __fmul_rn(y, r));
    y = __fadd_rn(r,  __fmul_rn(y, zz));
    y = __fadd_rn(1.0f, y);
    int k = (int)fx;
    float pow2 = __int_as_float((k + 127) << 23);
    float res = __fmul_rn(y, pow2);
    return fmaxf(res, x);
}

// ---------------- kernel 1: validity mask + per-batch partial histograms ----------------
__global__ void k_mask_hist(const float* __restrict__ score,
                            const float4* __restrict__ anchors) {
    __shared__ int sh[NBUCKET];
    for (int i = threadIdx.x; i < NBUCKET; i += NTHR) sh[i] = 0;
    __syncthreads();
    int b = blockIdx.y;
    int base = blockIdx.x * (NA / NPART);
    #pragma unroll
    for (int k = 0; k < (NA / NPART) / NTHR; k++) {
        int i = base + k * NTHR + threadIdx.x;
        float4 a = anchors[i];
        bool valid = (a.z <= 1.0f) && (a.w <= 1.0f) && (a.x >= 0.0f) && (a.y >= 0.0f);
        float s = score[(size_t)b * NA + i];
        float ms = valid ? s : -1.0f;
        atomicAdd(&sh[bucketOf(ms)], 1);
    }
    __syncthreads();
    for (int i = threadIdx.x; i < NBUCKET; i += NTHR)
        g_histpart[blockIdx.x][b][i] = sh[i];
}

// ---------------- kernel 2: per-batch threshold bucket (1 block per batch) ----------------
__global__ void k_findthr() {
    __shared__ int tot[NBUCKET];
    int b = blockIdx.x;
    for (int j = 0; j < NBUCKET / NTHR; j++) {
        int bucket = j * NTHR + threadIdx.x;
        int s = 0;
        #pragma unroll
        for (int p = 0; p < NPART; p++) s += g_histpart[p][b][bucket];
        tot[bucket] = s;
    }
    if (threadIdx.x == 0) g_candcnt[b] = 0;
    __syncthreads();
    if (threadIdx.x < 32) {
        int lane = threadIdx.x;
        int cum = 0;
        for (int c = NBUCKET / 32 - 1; c >= 0; --c) {
            int cnt = tot[c * 32 + lane];
            int s = cnt;
            #pragma unroll
            for (int off = 1; off < 32; off <<= 1) {
                int t = __shfl_down_sync(0xffffffffu, s, off);
                if (lane + off < 32) s += t;
            }
            int chunkSum = __shfl_sync(0xffffffffu, s, 0);
            if (cum + chunkSum >= KSEL) {
                bool pred = (cum + s) >= KSEL;
                unsigned bal = __ballot_sync(0xffffffffu, pred);
                int bl = 31 - __clz(bal);
                if (lane == 0) g_thr[b] = c * 32 + bl;
                return;
            }
            cum += chunkSum;
        }
        if (lane == 0) g_thr[b] = 0;
    }
}

// ---------------- kernel 3: compact candidates (bucket >= threshold) ----------------
__global__ void k_compact(const float* __restrict__ score,
                          const float4* __restrict__ anchors) {
    int b = blockIdx.y;
    int thr = g_thr[b];
    int base = blockIdx.x * (NA / 64);
    #pragma unroll
    for (int k = 0; k < (NA / 64) / 512; k++) {
        int i = base + k * 512 + threadIdx.x;
        float4 a = anchors[i];
        bool valid = (a.z <= 1.0f) && (a.w <= 1.0f) && (a.x >= 0.0f) && (a.y >= 0.0f);
        float s = score[(size_t)b * NA + i];
        float ms = valid ? s : -1.0f;
        if (bucketOf(ms) >= thr) {
            int p = atomicAdd(&g_candcnt[b], 1);
            if (p < SORTN) {
                g_candkey[b][p] =
                    ((unsigned long long)orderable(ms) << 32) | (unsigned)(NA - 1 - i);
            }
        }
    }
}

// ---------------- kernel 4: sort + decode + Morton sort + soft-NMS ----------------
extern __shared__ unsigned char smem_raw[];

__global__ void __launch_bounds__(NTHR, 1)
k_sortnms(const float4* __restrict__ regress,
          const float4* __restrict__ anchors,
          float4* __restrict__ out) {
    unsigned long long* keys = (unsigned long long*)smem_raw;            // 8192 u64
    float4* boxes  = (float4*)(smem_raw + (size_t)SORTN * 8);            // KPAD float4 (by rank)
    float*  scores = (float*) (smem_raw + (size_t)SORTN * 8 + (size_t)KPAD * 16); // KPAD f32
    __shared__ unsigned long long s_wmax[32];
    __shared__ unsigned long long s_best;

    int b = blockIdx.x;
    int tid = threadIdx.x;
    int lane = tid & 31;
    int wid = tid >> 5;

    // ---- load candidates, pad with 0 ----
    int cnt = g_candcnt[b];
    if (cnt > SORTN) cnt = SORTN;
    for (int i = tid; i < SORTN; i += NTHR)
        keys[i] = (i < cnt) ? g_candkey[b][i] : 0ULL;
    __syncthreads();

    // ---- bitonic sort #1: DESCENDING (score desc, orig idx asc) ----
    for (int k = 2; k <= SORTN; k <<= 1) {
        for (int j = k >> 1; j > 0; j >>= 1) {
            for (int i = tid; i < SORTN; i += NTHR) {
                int ixj = i ^ j;
                if (ixj > i) {
                    unsigned long long a = keys[i], c = keys[ixj];
                    bool sw = ((i & k) == 0) ? (a < c) : (a > c);
                    if (sw) { keys[i] = c; keys[ixj] = a; }
                }
            }
            __syncthreads();
        }
    }

    // ---- decode ranks [0,KSEL): delta2bbox + clip (exact RN); build Morton keys ----
    const float MR = (float)4.135166556742356;   // abs(log(16/1000))
#pragma unroll
    for (int k = 0; k < 5; k++) {
        int slot = tid + k * NTHR;                // 0..5119, slot == rank
        unsigned long long mkey;
        if (slot < KSEL) {
            unsigned long long key = keys[slot];
            unsigned idx = (unsigned)(NA - 1) - (unsigned)(key & 0xFFFFFFFFull);
            float s = fromOrderable((unsigned)(key >> 32));
            float4 t = regress[(size_t)b * NA + idx];
            float4 a = anchors[idx];
            float d0 = __fadd_rn(__fmul_rn(t.x, 0.1f), 0.0f);
            float d1 = __fadd_rn(__fmul_rn(t.y, 0.1f), 0.0f);
            float d2 = __fadd_rn(__fmul_rn(t.z, 0.2f), 0.0f);
            float d3 = __fadd_rn(__fmul_rn(t.w, 0.2f), 0.0f);
            d2 = fminf(fmaxf(d2, -MR), MR);
            d3 = fminf(fmaxf(d3, -MR), MR);
            float awx = __fsub_rn(a.z, a.x), awy = __fsub_rn(a.w, a.y);
            float acx = __fmul_rn(__fadd_rn(a.z, a.x), 0.5f);
            float acy = __fmul_rn(__fadd_rn(a.w, a.y), 0.5f);
            float cx = __fadd_rn(acx, __fmul_rn(d0, awx));
            float cy = __fadd_rn(acy, __fmul_rn(d1, awy));
            float wx = __fmul_rn(awx, xla_expf(d2));
            float wy = __fmul_rn(awy, xla_expf(d3));
            float x1 = __fsub_rn(cx, __fmul_rn(wx, 0.5f));
            float y1 = __fsub_rn(cy, __fmul_rn(wy, 0.5f));
            float x2 = __fadd_rn(cx, __fmul_rn(wx, 0.5f));
            float y2 = __fadd_rn(cy, __fmul_rn(wy, 0.5f));
            x1 = fminf(fmaxf(x1, 0.f), 1.f);
            y1 = fminf(fmaxf(y1, 0.f), 1.f);
            x2 = fminf(fmaxf(x2, 0.f), 1.f);
            y2 = fminf(fmaxf(y2, 0.f), 1.f);
            boxes[slot]  = make_float4(x1, y1, x2, y2);
            scores[slot] = s;
            // Morton of center (perf only, no exactness requirement)
            float mcx = (x1 + x2) * 0.5f, mcy = (y1 + y2) * 0.5f;
            unsigned xb = (unsigned)fminf(fmaxf(mcx * 1024.0f, 0.0f), 1023.0f);
            unsigned yb = (unsigned)fminf(fmaxf(mcy * 1024.0f, 0.0f), 1023.0f);
            unsigned mort = (part1by1(yb) << 1) | part1by1(xb);
            mkey = ((unsigned long long)mort << 13) | (unsigned)slot;
        } else {
            boxes[slot]  = make_float4(0.f, 0.f, 0.f, 0.f);
            scores[slot] = NEGV;
            mkey = (0xFFFFFULL << 13) | (unsigned)slot;   // dummies to the end
        }
        keys[slot] = mkey;    // safe: each slot touched by exactly one thread
    }
    for (int i = KPAD + tid; i < SORTN; i += NTHR) keys[i] = ~0ULL;
    __syncthreads();

    // ---- bitonic sort #2: ASCENDING by Morton (spatial clustering) ----
    for (int k = 2; k <= SORTN; k <<= 1) {
        for (int j = k >> 1; j > 0; j >>= 1) {
            for (int i = tid; i < SORTN; i += NTHR) {
                int ixj = i ^ j;
                if (ixj > i) {
                    unsigned long long a = keys[i], c = keys[ixj];
                    bool sw = ((i & k) == 0) ? (a > c) : (a < c);
                    if (sw) { keys[i] = c; keys[ixj] = a; }
                }
            }
            __syncthreads();
        }
    }

    // ---- take ownership: 5 CONTIGUOUS sorted slots per thread ----
    float msc[5]; int mrank[5];
    float tbx1 = 1e9f, tby1 = 1e9f, tbx2 = -1e9f, tby2 = -1e9f;
#pragma unroll
    for (int k = 0; k < 5; k++) {
        int p = tid * 5 + k;                       // < 5120
        int r = (int)(keys[p] & 0x1FFFULL);
        mrank[k] = r;
        msc[k] = scores[r];
        if (r < KSEL) {
            float4 bb = boxes[r];
            tbx1 = fminf(tbx1, bb.x); tby1 = fminf(tby1, bb.y);
            tbx2 = fmaxf(tbx2, bb.z); tby2 = fmaxf(tby2, bb.w);
        }
    }
    // cached thread-max argmax key
    unsigned long long tkey = 0ULL;
#pragma unroll
    for (int k = 0; k < 5; k++) {
        unsigned long long kk = ((unsigned long long)orderable(msc[k]) << 32)
                              | (unsigned)(SORTN - 1 - mrank[k]);
        if (kk > tkey) tkey = kk;
    }
    // warp max -> s_wmax
    {
        unsigned long long v = tkey;
#pragma unroll
        for (int off = 16; off; off >>= 1) {
            unsigned long long o = __shfl_down_sync(0xffffffffu, v, off);
            if (o > v) v = o;
        }
        if (lane == 0) s_wmax[wid] = v;
    }
    // warp bbox (union of thread bboxes)
    float wbx1 = tbx1, wby1 = tby1, wbx2 = tbx2, wby2 = tby2;
#pragma unroll
    for (int off = 16; off; off >>= 1) {
        wbx1 = fminf(wbx1, __shfl_xor_sync(0xffffffffu, wbx1, off));
        wby1 = fminf(wby1, __shfl_xor_sync(0xffffffffu, wby1, off));
        wbx2 = fmaxf(wbx2, __shfl_xor_sync(0xffffffffu, wbx2, off));
        wby2 = fmaxf(wby2, __shfl_xor_sync(0xffffffffu, wby2, off));
    }
    __syncthreads();

    // ---- soft-NMS: 1000 strictly sequential iterations ----
    for (int it = 0; it < NOUT; ++it) {
        // block argmax from cached per-warp maxima
        if (wid == 0) {
            unsigned long long v = s_wmax[lane];
#pragma unroll
            for (int off = 16; off; off >>= 1) {
                unsigned long long o = __shfl_down_sync(0xffffffffu, v, off);
                if (o > v) v = o;
            }
            if (lane == 0) s_best = v;
        }
        __syncthreads();

        unsigned long long bk = s_best;
        int pickrank = (SORTN - 1) - (int)(unsigned)(bk & 0xFFFFFFFFull);
        float ps = fromOrderable((unsigned)(bk >> 32));
        float4 pb = boxes[pickrank];               // broadcast LDS

        if (tid == 0)
            out[b * NOUT + it] = (ps > NEGV * 0.5f) ? pb : make_float4(0.f, 0.f, 0.f, 0.f);

        // warp-level spatial skip (exact: bbox-miss => inter==0 => factor==1.0)
        bool wact = (fminf(pb.z, wbx2) > fmaxf(pb.x, wbx1)) &&
                    (fminf(pb.w, wby2) > fmaxf(pb.y, wby1));
        if (wact) {
            float parea = __fmul_rn(__fsub_rn(pb.z, pb.x), __fsub_rn(pb.w, pb.y));
            bool changed = false;
            bool tact = (fminf(pb.z, tbx2) > fmaxf(pb.x, tbx1)) &&
                        (fminf(pb.w, tby2) > fmaxf(pb.y, tby1));
            if (tact) {
                // ---- BRANCHLESS rescore: stage all 5 elements for ILP ----
                float inter[5], den[5], fsc[5];
#pragma unroll
                for (int k = 0; k < 5; k++) {
                    float4 bb = boxes[mrank[k]];   // gathered LDS (active path only)
                    float ltx = fmaxf(pb.x, bb.x), lty = fmaxf(pb.y, bb.y);
                    float rbx = fminf(pb.z, bb.z), rby = fminf(pb.w, bb.w);
                    float iw = fmaxf(__fsub_rn(rbx, ltx), 0.0f);
                    float ih = fmaxf(__fsub_rn(rby, lty), 0.0f);
                    inter[k] = __fmul_rn(iw, ih);
                    float barea = __fmul_rn(__fsub_rn(bb.z, bb.x), __fsub_rn(bb.w, bb.y));
                    den[k] = __fadd_rn(__fsub_rn(__fadd_rn(parea, barea), inter[k]), 1e-12f);
                }
                // 5 independent divides: pipeline through MUFU/FMA
#pragma unroll
                for (int k = 0; k < 5; k++) {
                    float iou = __fdiv_rn(inter[k], den[k]);   // den >= 1e-12 > 0 always
                    fsc[k] = -__fmul_rn(iou, iou);             // == -0.5*iou*iou/0.5 exactly
                }
                // 5 interleaved exp chains (5-way ILP through the Horner ladder)
#pragma unroll
                for (int k = 0; k < 5; k++) fsc[k] = xla_expf(fsc[k]);
                // select-update: bitwise identical to the branchy form
#pragma unroll
                for (int k = 0; k < 5; k++) {
                    float ns = __fmul_rn(msc[k], fsc[k]);
                    bool hit = inter[k] > 0.0f;
                    msc[k] = hit ? ns : msc[k];
                    changed |= hit;
                    if (mrank[k] == pickrank) { msc[k] = NEGV; changed = true; }
                }
            }
            if (__ballot_sync(0xffffffffu, changed)) {
                if (changed) {
                    tkey = 0ULL;
#pragma unroll
                    for (int k = 0; k < 5; k++) {
                        unsigned long long kk =
                            ((unsigned long long)orderable(msc[k]) << 32)
                            | (unsigned)(SORTN - 1 - mrank[k]);
                        if (kk > tkey) tkey = kk;
                    }
                }
                unsigned long long v = tkey;
#pragma unroll
                for (int off = 16; off; off >>= 1) {
                    unsigned long long o = __shfl_down_sync(0xffffffffu, v, off);
                    if (o > v) v = o;
                }
                if (lane == 0) s_wmax[wid] = v;
            }
        }
        __syncthreads();
    }
}

// ---------------- launch ----------------
extern "C" void kernel_launch(void* const* d_in, const int* in_sizes, int n_in,
                              void* d_out, int out_size) {
    const float*  score   = (const float*)d_in[0];
    const float4* regress = (const float4*)d_in[1];
    const float4* anchors = (const float4*)d_in[2];
    float4* out = (float4*)d_out;

    const int smem_bytes = SORTN * 8 + KPAD * 16 + KPAD * 4;  // 167936
    cudaFuncSetAttribute(k_sortnms, cudaFuncAttributeMaxDynamicSharedMemorySize, smem_bytes);

    k_mask_hist<<<dim3(NPART, BATCH), NTHR>>>(score, anchors);
    k_findthr<<<BATCH, NTHR>>>();
    k_compact<<<dim3(64, BATCH), 512>>>(score, anchors);
    k_sortnms<<<BATCH, NTHR, smem_bytes>>>(regress, anchors, out);
}

// round 15
// speedup vs baseline: 1.1703x; 1.1703x over previous
#include <cuda_runtime.h>
#include <math.h>

#define BATCH   8
#define NA      262144
#define KSEL    5000
#define KPAD    5120
#define SORTN   8192
#define NBUCKET 4096
#define NOUT    1000
#define NEGV    (-1000000000.0f)
#define NTHR    1024
#define NPART   32

// ---------------- device-global scratch (no allocations allowed) ----------------
__device__ int                g_histpart[NPART][BATCH][NBUCKET];
__device__ int                g_thr[BATCH];
__device__ int                g_candcnt[BATCH];
__device__ unsigned long long g_candkey[BATCH][SORTN];

// ---------------- helpers ----------------
static __device__ __forceinline__ unsigned orderable(float f) {
    unsigned u = __float_as_uint(f);
    return (u & 0x80000000u) ? ~u : (u | 0x80000000u);
}
static __device__ __forceinline__ float fromOrderable(unsigned k) {
    return __uint_as_float((k & 0x80000000u) ? (k ^ 0x80000000u) : ~k);
}
static __device__ __forceinline__ int bucketOf(float s) {
    int b = (int)(s * 4096.0f);
    b = b < 0 ? 0 : b;
    return b > (NBUCKET - 1) ? (NBUCKET - 1) : b;
}
static __device__ __forceinline__ unsigned part1by1(unsigned v) {
    v &= 0x0000FFFFu;
    v = (v | (v << 8)) & 0x00FF00FFu;
    v = (v | (v << 4)) & 0x0F0F0F0Fu;
    v = (v | (v << 2)) & 0x33333333u;
    v = (v | (v << 1)) & 0x55555555u;
    return v;
}

// Bit-exact replica of XLA:CPU's f32 exp (GenerateVF32Exp): Cephes-style
// Horner with UNFUSED mul+add. Inputs in [-4.14, 4.14]; clamp omitted.
// The reference ends with max(res, x); for all finite x, exp(x) - x >= 1 and
// f32 rounding cannot close a gap of 1, so res > x always => max is identity
// and is omitted (shortens the serial dependency chain by one op).
static __device__ __forceinline__ float xla_expf(float x) {
    const float LOG2EF = 1.44269504088896341f;
    const float C1 = 0.693359375f;
    const float C2 = -2.12194440e-4f;
    const float p0 = 1.9875691500E-4f;
    const float p1 = 1.3981999507E-3f;
    const float p2 = 8.3334519073E-3f;
    const float p3 = 4.1665795894E-2f;
    const float p4 = 1.6666665459E-1f;
    const float p5 = 5.0000001201E-1f;
    float fx = floorf(__fadd_rn(0.5f, __fmul_rn(x, LOG2EF)));
    float tmp = __fmul_rn(C1, fx);
    float z0  = __fmul_rn(C2, fx);
    float r = __fsub_rn(x, tmp);
    r = __fsub_rn(r, z0);
    float zz = __fmul_rn(r, r);
    float y;
    y = __fadd_rn(p1, __fmul_rn(r, p0));
    y = __fadd_rn(p2, __fmul_rn(y, r));
    y = __fadd_rn(p3, __fmul_rn(y, r));
    y = __fadd_rn(p4, __fmul_rn(y, r));
    y = __fadd_rn(p5, __fmul_rn(y, r));
    y = __fadd_rn(r,  __fmul_rn(y, zz));
    y = __fadd_rn(1.0f, y);
    int k = (int)fx;
    float pow2 = __int_as_float((k + 127) << 23);
    return __fmul_rn(y, pow2);
}

// ---------------- kernel 1: validity mask + per-batch partial histograms ----------------
__global__ void k_mask_hist(const float* __restrict__ score,
                            const float4* __restrict__ anchors) {
    __shared__ int sh[NBUCKET];
    for (int i = threadIdx.x; i < NBUCKET; i += NTHR) sh[i] = 0;
    __syncthreads();
    int b = blockIdx.y;
    int base = blockIdx.x * (NA / NPART);
    #pragma unroll
    for (int k = 0; k < (NA / NPART) / NTHR; k++) {
        int i = base + k * NTHR + threadIdx.x;
        float4 a = anchors[i];
        bool valid = (a.z <= 1.0f) && (a.w <= 1.0f) && (a.x >= 0.0f) && (a.y >= 0.0f);
        float s = score[(size_t)b * NA + i];
        float ms = valid ? s : -1.0f;
        atomicAdd(&sh[bucketOf(ms)], 1);
    }
    __syncthreads();
    for (int i = threadIdx.x; i < NBUCKET; i += NTHR)
        g_histpart[blockIdx.x][b][i] = sh[i];
}

// ---------------- kernel 2: per-batch threshold bucket (1 block per batch) ----------------
__global__ void k_findthr() {
    __shared__ int tot[NBUCKET];
    int b = blockIdx.x;
    for (int j = 0; j < NBUCKET / NTHR; j++) {
        int bucket = j * NTHR + threadIdx.x;
        int s = 0;
        #pragma unroll
        for (int p = 0; p < NPART; p++) s += g_histpart[p][b][bucket];
        tot[bucket] = s;
    }
    if (threadIdx.x == 0) g_candcnt[b] = 0;
    __syncthreads();
    if (threadIdx.x < 32) {
        int lane = threadIdx.x;
        int cum = 0;
        for (int c = NBUCKET / 32 - 1; c >= 0; --c) {
            int cnt = tot[c * 32 + lane];
            int s = cnt;
            #pragma unroll
            for (int off = 1; off < 32; off <<= 1) {
                int t = __shfl_down_sync(0xffffffffu, s, off);
                if (lane + off < 32) s += t;
            }
            int chunkSum = __shfl_sync(0xffffffffu, s, 0);
            if (cum + chunkSum >= KSEL) {
                bool pred = (cum + s) >= KSEL;
                unsigned bal = __ballot_sync(0xffffffffu, pred);
                int bl = 31 - __clz(bal);
                if (lane == 0) g_thr[b] = c * 32 + bl;
                return;
            }
            cum += chunkSum;
        }
        if (lane == 0) g_thr[b] = 0;
    }
}

// ---------------- kernel 3: compact candidates (bucket >= threshold) ----------------
__global__ void k_compact(const float* __restrict__ score,
                          const float4* __restrict__ anchors) {
    int b = blockIdx.y;
    int thr = g_thr[b];
    int base = blockIdx.x * (NA / 64);
    #pragma unroll
    for (int k = 0; k < (NA / 64) / 512; k++) {
        int i = base + k * 512 + threadIdx.x;
        float4 a = anchors[i];
        bool valid = (a.z <= 1.0f) && (a.w <= 1.0f) && (a.x >= 0.0f) && (a.y >= 0.0f);
        float s = score[(size_t)b * NA + i];
        float ms = valid ? s : -1.0f;
        if (bucketOf(ms) >= thr) {
            int p = atomicAdd(&g_candcnt[b], 1);
            if (p < SORTN) {
                g_candkey[b][p] =
                    ((unsigned long long)orderable(ms) << 32) | (unsigned)(NA - 1 - i);
            }
        }
    }
}

// ---------------- kernel 4: sort + decode + Morton sort + soft-NMS ----------------
extern __shared__ unsigned char smem_raw[];

__global__ void __launch_bounds__(NTHR, 1)
k_sortnms(const float4* __restrict__ regress,
          const float4* __restrict__ anchors,
          float4* __restrict__ out) {
    unsigned long long* keys = (unsigned long long*)smem_raw;            // 8192 u64
    float4* boxes  = (float4*)(smem_raw + (size_t)SORTN * 8);            // KPAD float4 (by rank)
    float*  scores = (float*) (smem_raw + (size_t)SORTN * 8 + (size_t)KPAD * 16); // KPAD f32
    __shared__ unsigned long long s_wmax[32];
    __shared__ unsigned long long s_best;

    int b = blockIdx.x;
    int tid = threadIdx.x;
    int lane = tid & 31;
    int wid = tid >> 5;

    // ---- load candidates, pad with 0 ----
    int cnt = g_candcnt[b];
    if (cnt > SORTN) cnt = SORTN;
    for (int i = tid; i < SORTN; i += NTHR)
        keys[i] = (i < cnt) ? g_candkey[b][i] : 0ULL;
    __syncthreads();

    // ---- bitonic sort #1: DESCENDING (score desc, orig idx asc) ----
    for (int k = 2; k <= SORTN; k <<= 1) {
        for (int j = k >> 1; j > 0; j >>= 1) {
            for (int i = tid; i < SORTN; i += NTHR) {
                int ixj = i ^ j;
                if (ixj > i) {
                    unsigned long long a = keys[i], c = keys[ixj];
                    bool sw = ((i & k) == 0) ? (a < c) : (a > c);
                    if (sw) { keys[i] = c; keys[ixj] = a; }
                }
            }
            __syncthreads();
        }
    }

    // ---- decode ranks [0,KSEL): delta2bbox + clip (exact RN); build Morton keys ----
    const float MR = (float)4.135166556742356;   // abs(log(16/1000))
#pragma unroll
    for (int k = 0; k < 5; k++) {
        int slot = tid + k * NTHR;                // 0..5119, slot == rank
        unsigned long long mkey;
        if (slot < KSEL) {
            unsigned long long key = keys[slot];
            unsigned idx = (unsigned)(NA - 1) - (unsigned)(key & 0xFFFFFFFFull);
            float s = fromOrderable((unsigned)(key >> 32));
            float4 t = regress[(size_t)b * NA + idx];
            float4 a = anchors[idx];
            float d0 = __fadd_rn(__fmul_rn(t.x, 0.1f), 0.0f);
            float d1 = __fadd_rn(__fmul_rn(t.y, 0.1f), 0.0f);
            float d2 = __fadd_rn(__fmul_rn(t.z, 0.2f), 0.0f);
            float d3 = __fadd_rn(__fmul_rn(t.w, 0.2f), 0.0f);
            d2 = fminf(fmaxf(d2, -MR), MR);
            d3 = fminf(fmaxf(d3, -MR), MR);
            float awx = __fsub_rn(a.z, a.x), awy = __fsub_rn(a.w, a.y);
            float acx = __fmul_rn(__fadd_rn(a.z, a.x), 0.5f);
            float acy = __fmul_rn(__fadd_rn(a.w, a.y), 0.5f);
            float cx = __fadd_rn(acx, __fmul_rn(d0, awx));
            float cy = __fadd_rn(acy, __fmul_rn(d1, awy));
            float wx = __fmul_rn(awx, xla_expf(d2));
            float wy = __fmul_rn(awy, xla_expf(d3));
            float x1 = __fsub_rn(cx, __fmul_rn(wx, 0.5f));
            float y1 = __fsub_rn(cy, __fmul_rn(wy, 0.5f));
            float x2 = __fadd_rn(cx, __fmul_rn(wx, 0.5f));
            float y2 = __fadd_rn(cy, __fmul_rn(wy, 0.5f));
            x1 = fminf(fmaxf(x1, 0.f), 1.f);
            y1 = fminf(fmaxf(y1, 0.f), 1.f);
            x2 = fminf(fmaxf(x2, 0.f), 1.f);
            y2 = fminf(fmaxf(y2, 0.f), 1.f);
            boxes[slot]  = make_float4(x1, y1, x2, y2);
            scores[slot] = s;
            // Morton of center (perf only, no exactness requirement)
            float mcx = (x1 + x2) * 0.5f, mcy = (y1 + y2) * 0.5f;
            unsigned xb = (unsigned)fminf(fmaxf(mcx * 1024.0f, 0.0f), 1023.0f);
            unsigned yb = (unsigned)fminf(fmaxf(mcy * 1024.0f, 0.0f), 1023.0f);
            unsigned mort = (part1by1(yb) << 1) | part1by1(xb);
            mkey = ((unsigned long long)mort << 13) | (unsigned)slot;
        } else {
            boxes[slot]  = make_float4(0.f, 0.f, 0.f, 0.f);
            scores[slot] = NEGV;
            mkey = (0xFFFFFULL << 13) | (unsigned)slot;   // dummies to the end
        }
        keys[slot] = mkey;    // safe: each slot touched by exactly one thread
    }
    for (int i = KPAD + tid; i < SORTN; i += NTHR) keys[i] = ~0ULL;
    __syncthreads();

    // ---- bitonic sort #2: ASCENDING by Morton (spatial clustering) ----
    for (int k = 2; k <= SORTN; k <<= 1) {
        for (int j = k >> 1; j > 0; j >>= 1) {
            for (int i = tid; i < SORTN; i += NTHR) {
                int ixj = i ^ j;
                if (ixj > i) {
                    unsigned long long a = keys[i], c = keys[ixj];
                    bool sw = ((i & k) == 0) ? (a > c) : (a < c);
                    if (sw) { keys[i] = c; keys[ixj] = a; }
                }
            }
            __syncthreads();
        }
    }

    // ---- take ownership: 5 CONTIGUOUS sorted slots per thread ----
    float msc[5]; int mrank[5];
    float tbx1 = 1e9f, tby1 = 1e9f, tbx2 = -1e9f, tby2 = -1e9f;
#pragma unroll
    for (int k = 0; k < 5; k++) {
        int p = tid * 5 + k;                       // < 5120
        int r = (int)(keys[p] & 0x1FFFULL);
        mrank[k] = r;
        msc[k] = scores[r];
        if (r < KSEL) {
            float4 bb = boxes[r];
            tbx1 = fminf(tbx1, bb.x); tby1 = fminf(tby1, bb.y);
            tbx2 = fmaxf(tbx2, bb.z); tby2 = fmaxf(tby2, bb.w);
        }
    }
    // cached thread-max argmax key
    unsigned long long tkey = 0ULL;
#pragma unroll
    for (int k = 0; k < 5; k++) {
        unsigned long long kk = ((unsigned long long)orderable(msc[k]) << 32)
                              | (unsigned)(SORTN - 1 - mrank[k]);
        if (kk > tkey) tkey = kk;
    }
    // warp max -> s_wmax
    {
        unsigned long long v = tkey;
#pragma unroll
        for (int off = 16; off; off >>= 1) {
            unsigned long long o = __shfl_down_sync(0xffffffffu, v, off);
            if (o > v) v = o;
        }
        if (lane == 0) s_wmax[wid] = v;
    }
    // warp bbox (union of thread bboxes)
    float wbx1 = tbx1, wby1 = tby1, wbx2 = tbx2, wby2 = tby2;
#pragma unroll
    for (int off = 16; off; off >>= 1) {
        wbx1 = fminf(wbx1, __shfl_xor_sync(0xffffffffu, wbx1, off));
        wby1 = fminf(wby1, __shfl_xor_sync(0xffffffffu, wby1, off));
        wbx2 = fmaxf(wbx2, __shfl_xor_sync(0xffffffffu, wbx2, off));
        wby2 = fmaxf(wby2, __shfl_xor_sync(0xffffffffu, wby2, off));
    }
    __syncthreads();

    // ---- soft-NMS: 1000 strictly sequential iterations ----
    for (int it = 0; it < NOUT; ++it) {
        // block argmax from cached per-warp maxima
        if (wid == 0) {
            unsigned long long v = s_wmax[lane];
#pragma unroll
            for (int off = 16; off; off >>= 1) {
                unsigned long long o = __shfl_down_sync(0xffffffffu, v, off);
                if (o > v) v = o;
            }
            if (lane == 0) s_best = v;
        }
        __syncthreads();

        unsigned long long bk = s_best;
        int pickrank = (SORTN - 1) - (int)(unsigned)(bk & 0xFFFFFFFFull);
        float ps = fromOrderable((unsigned)(bk >> 32));
        float4 pb = boxes[pickrank];               // broadcast LDS

        if (tid == 0)
            out[b * NOUT + it] = (ps > NEGV * 0.5f) ? pb : make_float4(0.f, 0.f, 0.f, 0.f);

        // warp-level spatial skip (exact: bbox-miss => inter==0 => factor==1.0)
        bool wact = (fminf(pb.z, wbx2) > fmaxf(pb.x, wbx1)) &&
                    (fminf(pb.w, wby2) > fmaxf(pb.y, wby1));
        if (wact) {
            float parea = __fmul_rn(__fsub_rn(pb.z, pb.x), __fsub_rn(pb.w, pb.y));
            bool changed = false;
            bool tact = (fminf(pb.z, tbx2) > fmaxf(pb.x, tbx1)) &&
                        (fminf(pb.w, tby2) > fmaxf(pb.y, tby1));
            if (tact) {
#pragma unroll
                for (int k = 0; k < 5; k++) {
                    // Dead/zero skip is EXACT: s<=0 stays <=0 under multiplication
                    // by f in (0,1] (+0*f==+0 bitwise; negatives stay negative),
                    // and >=4000 strictly positive live scores always remain, so a
                    // frozen dead element can never win the argmax => no pick and
                    // no output changes.
                    if (msc[k] > 0.0f) {
                        float4 bb = boxes[mrank[k]];   // gathered LDS (live, active path)
                        float ltx = fmaxf(pb.x, bb.x), lty = fmaxf(pb.y, bb.y);
                        float rbx = fminf(pb.z, bb.z), rby = fminf(pb.w, bb.w);
                        float iw = fmaxf(__fsub_rn(rbx, ltx), 0.0f);
                        float ih = fmaxf(__fsub_rn(rby, lty), 0.0f);
                        float inter = __fmul_rn(iw, ih);
                        if (inter > 0.0f) {
                            float barea = __fmul_rn(__fsub_rn(bb.z, bb.x),
                                                    __fsub_rn(bb.w, bb.y));
                            float den = __fadd_rn(__fsub_rn(__fadd_rn(parea, barea), inter), 1e-12f);
                            float iou = __fdiv_rn(inter, den);
                            float arg = -__fmul_rn(iou, iou);   // == -0.5*iou*iou/0.5 exactly
                            msc[k] = __fmul_rn(msc[k], xla_expf(arg));
                            changed = true;
                        }
                        if (mrank[k] == pickrank) { msc[k] = NEGV; changed = true; }
                    }
                }
            }
            if (__ballot_sync(0xffffffffu, changed)) {
                if (changed) {
                    tkey = 0ULL;
#pragma unroll
                    for (int k = 0; k < 5; k++) {
                        unsigned long long kk =
                            ((unsigned long long)orderable(msc[k]) << 32)
                            | (unsigned)(SORTN - 1 - mrank[k]);
                        if (kk > tkey) tkey = kk;
                    }
                }
                unsigned long long v = tkey;
#pragma unroll
                for (int off = 16; off; off >>= 1) {
                    unsigned long long o = __shfl_down_sync(0xffffffffu, v, off);
                    if (o > v) v = o;
                }
                if (lane == 0) s_wmax[wid] = v;
            }
        }
        __syncthreads();
    }
}

// ---------------- launch ----------------
extern "C" void kernel_launch(void* const* d_in, const int* in_sizes, int n_in,
                              void* d_out, int out_size) {
    const float*  score   = (const float*)d_in[0];
    const float4* regress = (const float4*)d_in[1];
    const float4* anchors = (const float4*)d_in[2];
    float4* out = (float4*)d_out;

    const int smem_bytes = SORTN * 8 + KPAD * 16 + KPAD * 4;  // 167936
    cudaFuncSetAttribute(k_sortnms, cudaFuncAttributeMaxDynamicSharedMemorySize, smem_bytes);

    k_mask_hist<<<dim3(NPART, BATCH), NTHR>>>(score, anchors);
    k_findthr<<<BATCH, NTHR>>>();
    k_compact<<<dim3(64, BATCH), 512>>>(score, anchors);
    k_sortnms<<<BATCH, NTHR, smem_bytes>>>(regress, anchors, out);
}

// round 16
// speedup vs baseline: 1.3441x; 1.1485x over previous
#include <cuda_runtime.h>
#include <math.h>

#define BATCH   8
#define NA      262144
#define KSEL    5000
#define KPAD    5120
#define SORTN   8192
#define NBUCKET 4096
#define NOUT    1000
#define NEGV    (-1000000000.0f)
#define NTHR    1024
#define NPART   32

// ---------------- device-global scratch (no allocations allowed) ----------------
__device__ int                g_histpart[NPART][BATCH][NBUCKET];
__device__ int                g_thr[BATCH];
__device__ int                g_candcnt[BATCH];
__device__ unsigned long long g_candkey[BATCH][SORTN];

// ---------------- helpers ----------------
static __device__ __forceinline__ unsigned orderable(float f) {
    unsigned u = __float_as_uint(f);
    return (u & 0x80000000u) ? ~u : (u | 0x80000000u);
}
static __device__ __forceinline__ float fromOrderable(unsigned k) {
    return __uint_as_float((k & 0x80000000u) ? (k ^ 0x80000000u) : ~k);
}
static __device__ __forceinline__ int bucketOf(float s) {
    int b = (int)(s * 4096.0f);
    b = b < 0 ? 0 : b;
    return b > (NBUCKET - 1) ? (NBUCKET - 1) : b;
}
static __device__ __forceinline__ unsigned part1by1(unsigned v) {
    v &= 0x0000FFFFu;
    v = (v | (v << 8)) & 0x00FF00FFu;
    v = (v | (v << 4)) & 0x0F0F0F0Fu;
    v = (v | (v << 2)) & 0x33333333u;
    v = (v | (v << 1)) & 0x55555555u;
    return v;
}

// Bit-exact replica of XLA:CPU's f32 exp (GenerateVF32Exp): Cephes-style
// Horner with UNFUSED mul+add. Inputs in [-4.14, 4.14]; clamp omitted.
static __device__ __forceinline__ float xla_expf(float x) {
    const float LOG2EF = 1.44269504088896341f;
    const float C1 = 0.693359375f;
    const float C2 = -2.12194440e-4f;
    const float p0 = 1.9875691500E-4f;
    const float p1 = 1.3981999507E-3f;
    const float p2 = 8.3334519073E-3f;
    const float p3 = 4.1665795894E-2f;
    const float p4 = 1.6666665459E-1f;
    const float p5 = 5.0000001201E-1f;
    float fx = floorf(__fadd_rn(0.5f, __fmul_rn(x, LOG2EF)));
    float tmp = __fmul_rn(C1, fx);
    float z0  = __fmul_rn(C2, fx);
    float r = __fsub_rn(x, tmp);
    r = __fsub_rn(r, z0);
    float zz = __fmul_rn(r, r);
    float y;
    y = __fadd_rn(p1, __fmul_rn(r, p0));
    y = __fadd_rn(p2, __fmul_rn(y, r));
    y = __fadd_rn(p3, __fmul_rn(y, r));
    y = __fadd_rn(p4, __fmul_rn(y, r));
    y = __fadd_rn(p5, __fmul_rn(y, r));
    y = __fadd_rn(r,  __fmul_rn(y, zz));
    y = __fadd_rn(1.0f, y);
    int k = (int)fx;
    float pow2 = __int_as_float((k + 127) << 23);
    float res = __fmul_rn(y, pow2);
    return fmaxf(res, x);
}

// ---------------- kernel 1: validity mask + per-batch partial histograms ----------------
__global__ void k_mask_hist(const float* __restrict__ score,
                            const float4* __restrict__ anchors) {
    __shared__ int sh[NBUCKET];
    for (int i = threadIdx.x; i < NBUCKET; i += NTHR) sh[i] = 0;
    __syncthreads();
    int b = blockIdx.y;
    int base = blockIdx.x * (NA / NPART);
    #pragma unroll
    for (int k = 0; k < (NA / NPART) / NTHR; k++) {
        int i = base + k * NTHR + threadIdx.x;
        float4 a = anchors[i];
        bool valid = (a.z <= 1.0f) && (a.w <= 1.0f) && (a.x >= 0.0f) && (a.y >= 0.0f);
        float s = score[(size_t)b * NA + i];
        float ms = valid ? s : -1.0f;
        atomicAdd(&sh[bucketOf(ms)], 1);
    }
    __syncthreads();
    for (int i = threadIdx.x; i < NBUCKET; i += NTHR)
        g_histpart[blockIdx.x][b][i] = sh[i];
}

// ---------------- kernel 2: per-batch threshold bucket (1 block per batch) ----------------
__global__ void k_findthr() {
    __shared__ int tot[NBUCKET];
    int b = blockIdx.x;
    for (int j = 0; j < NBUCKET / NTHR; j++) {
        int bucket = j * NTHR + threadIdx.x;
        int s = 0;
        #pragma unroll
        for (int p = 0; p < NPART; p++) s += g_histpart[p][b][bucket];
        tot[bucket] = s;
    }
    if (threadIdx.x == 0) g_candcnt[b] = 0;
    __syncthreads();
    if (threadIdx.x < 32) {
        int lane = threadIdx.x;
        int cum = 0;
        for (int c = NBUCKET / 32 - 1; c >= 0; --c) {
            int cnt = tot[c * 32 + lane];
            int s = cnt;
            #pragma unroll
            for (int off = 1; off < 32; off <<= 1) {
                int t = __shfl_down_sync(0xffffffffu, s, off);
                if (lane + off < 32) s += t;
            }
            int chunkSum = __shfl_sync(0xffffffffu, s, 0);
            if (cum + chunkSum >= KSEL) {
                bool pred = (cum + s) >= KSEL;
                unsigned bal = __ballot_sync(0xffffffffu, pred);
                int bl = 31 - __clz(bal);
                if (lane == 0) g_thr[b] = c * 32 + bl;
                return;
            }
            cum += chunkSum;
        }
        if (lane == 0) g_thr[b] = 0;
    }
}

// ---------------- kernel 3: compact candidates (bucket >= threshold) ----------------
__global__ void k_compact(const float* __restrict__ score,
                          const float4* __restrict__ anchors) {
    int b = blockIdx.y;
    int thr = g_thr[b];
    int base = blockIdx.x * (NA / 64);
    #pragma unroll
    for (int k = 0; k < (NA / 64) / 512; k++) {
        int i = base + k * 512 + threadIdx.x;
        float4 a = anchors[i];
        bool valid = (a.z <= 1.0f) && (a.w <= 1.0f) && (a.x >= 0.0f) && (a.y >= 0.0f);
        float s = score[(size_t)b * NA + i];
        float ms = valid ? s : -1.0f;
        if (bucketOf(ms) >= thr) {
            int p = atomicAdd(&g_candcnt[b], 1);
            if (p < SORTN) {
                g_candkey[b][p] =
                    ((unsigned long long)orderable(ms) << 32) | (unsigned)(NA - 1 - i);
            }
        }
    }
}

// ---------------- kernel 4: sort + decode + Morton sort + soft-NMS ----------------
extern __shared__ unsigned char smem_raw[];

__global__ void __launch_bounds__(NTHR, 1)
k_sortnms(const float4* __restrict__ regress,
          const float4* __restrict__ anchors,
          float4* __restrict__ out) {
    unsigned long long* keys = (unsigned long long*)smem_raw;            // 8192 u64
    float4* boxes  = (float4*)(smem_raw + (size_t)SORTN * 8);            // KPAD float4 (by rank)
    float*  scores = (float*) (smem_raw + (size_t)SORTN * 8 + (size_t)KPAD * 16); // KPAD f32
    __shared__ unsigned long long s_wmax[32];
    __shared__ unsigned long long s_best;

    int b = blockIdx.x;
    int tid = threadIdx.x;
    int lane = tid & 31;
    int wid = tid >> 5;

    // ---- load candidates, pad with 0 ----
    int cnt = g_candcnt[b];
    if (cnt > SORTN) cnt = SORTN;
    for (int i = tid; i < SORTN; i += NTHR)
        keys[i] = (i < cnt) ? g_candkey[b][i] : 0ULL;
    __syncthreads();

    // ---- bitonic sort #1: DESCENDING (score desc, orig idx asc) ----
    for (int k = 2; k <= SORTN; k <<= 1) {
        for (int j = k >> 1; j > 0; j >>= 1) {
            for (int i = tid; i < SORTN; i += NTHR) {
                int ixj = i ^ j;
                if (ixj > i) {
                    unsigned long long a = keys[i], c = keys[ixj];
                    bool sw = ((i & k) == 0) ? (a < c) : (a > c);
                    if (sw) { keys[i] = c; keys[ixj] = a; }
                }
            }
            __syncthreads();
        }
    }

    // ---- decode ranks [0,KSEL): delta2bbox + clip (exact RN); build Morton keys ----
    const float MR = (float)4.135166556742356;   // abs(log(16/1000))
#pragma unroll
    for (int k = 0; k < 5; k++) {
        int slot = tid + k * NTHR;                // 0..5119, slot == rank
        unsigned long long mkey;
        if (slot < KSEL) {
            unsigned long long key = keys[slot];
            unsigned idx = (unsigned)(NA - 1) - (unsigned)(key & 0xFFFFFFFFull);
            float s = fromOrderable((unsigned)(key >> 32));
            float4 t = regress[(size_t)b * NA + idx];
            float4 a = anchors[idx];
            float d0 = __fadd_rn(__fmul_rn(t.x, 0.1f), 0.0f);
            float d1 = __fadd_rn(__fmul_rn(t.y, 0.1f), 0.0f);
            float d2 = __fadd_rn(__fmul_rn(t.z, 0.2f), 0.0f);
            float d3 = __fadd_rn(__fmul_rn(t.w, 0.2f), 0.0f);
            d2 = fminf(fmaxf(d2, -MR), MR);
            d3 = fminf(fmaxf(d3, -MR), MR);
            float awx = __fsub_rn(a.z, a.x), awy = __fsub_rn(a.w, a.y);
            float acx = __fmul_rn(__fadd_rn(a.z, a.x), 0.5f);
            float acy = __fmul_rn(__fadd_rn(a.w, a.y), 0.5f);
            float cx = __fadd_rn(acx, __fmul_rn(d0, awx));
            float cy = __fadd_rn(acy, __fmul_rn(d1, awy));
            float wx = __fmul_rn(awx, xla_expf(d2));
            float wy = __fmul_rn(awy, xla_expf(d3));
            float x1 = __fsub_rn(cx, __fmul_rn(wx, 0.5f));
            float y1 = __fsub_rn(cy, __fmul_rn(wy, 0.5f));
            float x2 = __fadd_rn(cx, __fmul_rn(wx, 0.5f));
            float y2 = __fadd_rn(cy, __fmul_rn(wy, 0.5f));
            x1 = fminf(fmaxf(x1, 0.f), 1.f);
            y1 = fminf(fmaxf(y1, 0.f), 1.f);
            x2 = fminf(fmaxf(x2, 0.f), 1.f);
            y2 = fminf(fmaxf(y2, 0.f), 1.f);
            boxes[slot]  = make_float4(x1, y1, x2, y2);
            scores[slot] = s;
            // Morton of center (perf only, no exactness requirement)
            float mcx = (x1 + x2) * 0.5f, mcy = (y1 + y2) * 0.5f;
            unsigned xb = (unsigned)fminf(fmaxf(mcx * 1024.0f, 0.0f), 1023.0f);
            unsigned yb = (unsigned)fminf(fmaxf(mcy * 1024.0f, 0.0f), 1023.0f);
            unsigned mort = (part1by1(yb) << 1) | part1by1(xb);
            mkey = ((unsigned long long)mort << 13) | (unsigned)slot;
        } else {
            boxes[slot]  = make_float4(0.f, 0.f, 0.f, 0.f);
            scores[slot] = NEGV;
            mkey = (0xFFFFFULL << 13) | (unsigned)slot;   // dummies to the end
        }
        keys[slot] = mkey;    // safe: each slot touched by exactly one thread
    }
    for (int i = KPAD + tid; i < SORTN; i += NTHR) keys[i] = ~0ULL;
    __syncthreads();

    // ---- bitonic sort #2: ASCENDING by Morton (spatial clustering) ----
    for (int k = 2; k <= SORTN; k <<= 1) {
        for (int j = k >> 1; j > 0; j >>= 1) {
            for (int i = tid; i < SORTN; i += NTHR) {
                int ixj = i ^ j;
                if (ixj > i) {
                    unsigned long long a = keys[i], c = keys[ixj];
                    bool sw = ((i & k) == 0) ? (a > c) : (a < c);
                    if (sw) { keys[i] = c; keys[ixj] = a; }
                }
            }
            __syncthreads();
        }
    }

    // ---- take ownership: 5 CONTIGUOUS sorted slots; boxes into REGISTERS ----
    float msc[5];
    float4 bx[5];            // loop-resident element boxes (no per-iter gathers)
    unsigned lowk[5];        // SORTN-1-rank (key low field; pick match by equality)
    float wbx1 = 1e9f, wby1 = 1e9f, wbx2 = -1e9f, wby2 = -1e9f;
#pragma unroll
    for (int k = 0; k < 5; k++) {
        int p = tid * 5 + k;                       // < 5120
        int r = (int)(keys[p] & 0x1FFFULL);
        lowk[k] = (unsigned)(SORTN - 1 - r);
        msc[k] = scores[r];
        bx[k]  = boxes[r];
        if (r < KSEL) {
            wbx1 = fminf(wbx1, bx[k].x); wby1 = fminf(wby1, bx[k].y);
            wbx2 = fmaxf(wbx2, bx[k].z); wby2 = fmaxf(wby2, bx[k].w);
        }
    }
    // cached thread-max argmax key
    unsigned long long tkey = 0ULL;
#pragma unroll
    for (int k = 0; k < 5; k++) {
        unsigned long long kk = ((unsigned long long)orderable(msc[k]) << 32) | lowk[k];
        if (kk > tkey) tkey = kk;
    }
    // warp max -> s_wmax
    {
        unsigned long long v = tkey;
#pragma unroll
        for (int off = 16; off; off >>= 1) {
            unsigned long long o = __shfl_down_sync(0xffffffffu, v, off);
            if (o > v) v = o;
        }
        if (lane == 0) s_wmax[wid] = v;
    }
    // warp bbox (union of thread bboxes)
#pragma unroll
    for (int off = 16; off; off >>= 1) {
        wbx1 = fminf(wbx1, __shfl_xor_sync(0xffffffffu, wbx1, off));
        wby1 = fminf(wby1, __shfl_xor_sync(0xffffffffu, wby1, off));
        wbx2 = fmaxf(wbx2, __shfl_xor_sync(0xffffffffu, wbx2, off));
        wby2 = fmaxf(wby2, __shfl_xor_sync(0xffffffffu, wby2, off));
    }
    __syncthreads();

    // ---- soft-NMS: 1000 strictly sequential iterations ----
    for (int it = 0; it < NOUT; ++it) {
        // block argmax from cached per-warp maxima
        if (wid == 0) {
            unsigned long long v = s_wmax[lane];
#pragma unroll
            for (int off = 16; off; off >>= 1) {
                unsigned long long o = __shfl_down_sync(0xffffffffu, v, off);
                if (o > v) v = o;
            }
            if (lane == 0) s_best = v;
        }
        __syncthreads();

        unsigned long long bk = s_best;
        unsigned picklo = (unsigned)(bk & 0xFFFFFFFFull);
        int pickrank = (SORTN - 1) - (int)picklo;
        float ps = fromOrderable((unsigned)(bk >> 32));
        float4 pb = boxes[pickrank];               // broadcast LDS

        if (tid == 0)
            out[b * NOUT + it] = (ps > NEGV * 0.5f) ? pb : make_float4(0.f, 0.f, 0.f, 0.f);

        // warp-level spatial skip (exact: bbox-miss => inter==0 => factor==1.0)
        bool wact = (fminf(pb.z, wbx2) > fmaxf(pb.x, wbx1)) &&
                    (fminf(pb.w, wby2) > fmaxf(pb.y, wby1));
        if (wact) {
            float parea = __fmul_rn(__fsub_rn(pb.z, pb.x), __fsub_rn(pb.w, pb.y));
            bool changed = false;
#pragma unroll
            for (int k = 0; k < 5; k++) {
                float ltx = fmaxf(pb.x, bx[k].x), lty = fmaxf(pb.y, bx[k].y);
                float rbx = fminf(pb.z, bx[k].z), rby = fminf(pb.w, bx[k].w);
                float iw = fmaxf(__fsub_rn(rbx, ltx), 0.0f);
                float ih = fmaxf(__fsub_rn(rby, lty), 0.0f);
                float inter = __fmul_rn(iw, ih);
                if (inter > 0.0f) {
                    float barea = __fmul_rn(__fsub_rn(bx[k].z, bx[k].x),
                                            __fsub_rn(bx[k].w, bx[k].y));
                    float den = __fadd_rn(__fsub_rn(__fadd_rn(parea, barea), inter), 1e-12f);
                    float iou = __fdiv_rn(inter, den);
                    float arg = -__fmul_rn(iou, iou);   // == -0.5*iou*iou/0.5 exactly
                    msc[k] = __fmul_rn(msc[k], xla_expf(arg));
                    changed = true;
                }
                if (lowk[k] == picklo) { msc[k] = NEGV; changed = true; }
            }
            if (__ballot_sync(0xffffffffu, changed)) {
                if (changed) {
                    tkey = 0ULL;
#pragma unroll
                    for (int k = 0; k < 5; k++) {
                        unsigned long long kk =
                            ((unsigned long long)orderable(msc[k]) << 32) | lowk[k];
                        if (kk > tkey) tkey = kk;
                    }
                }
                unsigned long long v = tkey;
#pragma unroll
                for (int off = 16; off; off >>= 1) {
                    unsigned long long o = __shfl_down_sync(0xffffffffu, v, off);
                    if (o > v) v = o;
                }
                if (lane == 0) s_wmax[wid] = v;
            }
        }
        __syncthreads();
    }
}

// ---------------- launch ----------------
extern "C" void kernel_launch(void* const* d_in, const int* in_sizes, int n_in,
                              void* d_out, int out_size) {
    const float*  score   = (const float*)d_in[0];
    const float4* regress = (const float4*)d_in[1];
    const float4* anchors = (const float4*)d_in[2];
    float4* out = (float4*)d_out;

    const int smem_bytes = SORTN * 8 + KPAD * 16 + KPAD * 4;  // 167936
    cudaFuncSetAttribute(k_sortnms, cudaFuncAttributeMaxDynamicSharedMemorySize, smem_bytes);

    k_mask_hist<<<dim3(NPART, BATCH), NTHR>>>(score, anchors);
    k_findthr<<<BATCH, NTHR>>>();
    k_compact<<<dim3(64, BATCH), 512>>>(score, anchors);
    k_sortnms<<<BATCH, NTHR, smem_bytes>>>(regress, anchors, out);
}

// round 17
// speedup vs baseline: 1.3642x; 1.0149x over previous
#include <cuda_runtime.h>
#include <math.h>

#define BATCH   8
#define NA      262144
#define KSEL    5000
#define KPAD    5120
#define SORTN   8192
#define NBUCKET 4096
#define NOUT    1000
#define NEGV    (-1000000000.0f)
#define NTHR    1024
#define NPART   32

// ---------------- device-global scratch (no allocations allowed) ----------------
__device__ int                g_histpart[NPART][BATCH][NBUCKET];
__device__ int                g_thr[BATCH];
__device__ int                g_candcnt[BATCH];
__device__ unsigned long long g_candkey[BATCH][SORTN];

// ---------------- helpers ----------------
static __device__ __forceinline__ unsigned orderable(float f) {
    unsigned u = __float_as_uint(f);
    return (u & 0x80000000u) ? ~u : (u | 0x80000000u);
}
static __device__ __forceinline__ float fromOrderable(unsigned k) {
    return __uint_as_float((k & 0x80000000u) ? (k ^ 0x80000000u) : ~k);
}
static __device__ __forceinline__ int bucketOf(float s) {
    int b = (int)(s * 4096.0f);
    b = b < 0 ? 0 : b;
    return b > (NBUCKET - 1) ? (NBUCKET - 1) : b;
}
static __device__ __forceinline__ unsigned part1by1(unsigned v) {
    v &= 0x0000FFFFu;
    v = (v | (v << 8)) & 0x00FF00FFu;
    v = (v | (v << 4)) & 0x0F0F0F0Fu;
    v = (v | (v << 2)) & 0x33333333u;
    v = (v | (v << 1)) & 0x55555555u;
    return v;
}

// Bit-exact replica of XLA:CPU's f32 exp (GenerateVF32Exp): Cephes-style
// Horner with UNFUSED mul+add. Inputs in [-4.14, 4.14]; clamp omitted.
// The reference ends with max(res, x); for all finite x, exp(x) - x >= 1 and
// f32 rounding cannot close a gap of 1, so res > x always => the max is a
// bitwise identity and is omitted (one op off the serial dependency chain).
static __device__ __forceinline__ float xla_expf(float x) {
    const float LOG2EF = 1.44269504088896341f;
    const float C1 = 0.693359375f;
    const float C2 = -2.12194440e-4f;
    const float p0 = 1.9875691500E-4f;
    const float p1 = 1.3981999507E-3f;
    const float p2 = 8.3334519073E-3f;
    const float p3 = 4.1665795894E-2f;
    const float p4 = 1.6666665459E-1f;
    const float p5 = 5.0000001201E-1f;
    float fx = floorf(__fadd_rn(0.5f, __fmul_rn(x, LOG2EF)));
    float tmp = __fmul_rn(C1, fx);
    float z0  = __fmul_rn(C2, fx);
    float r = __fsub_rn(x, tmp);
    r = __fsub_rn(r, z0);
    float zz = __fmul_rn(r, r);
    float y;
    y = __fadd_rn(p1, __fmul_rn(r, p0));
    y = __fadd_rn(p2, __fmul_rn(y, r));
    y = __fadd_rn(p3, __fmul_rn(y, r));
    y = __fadd_rn(p4, __fmul_rn(y, r));
    y = __fadd_rn(p5, __fmul_rn(y, r));
    y = __fadd_rn(r,  __fmul_rn(y, zz));
    y = __fadd_rn(1.0f, y);
    int k = (int)fx;
    float pow2 = __int_as_float((k + 127) << 23);
    return __fmul_rn(y, pow2);
}

// ---------------- kernel 1: validity mask + per-batch partial histograms ----------------
__global__ void k_mask_hist(const float* __restrict__ score,
                            const float4* __restrict__ anchors) {
    __shared__ int sh[NBUCKET];
    for (int i = threadIdx.x; i < NBUCKET; i += NTHR) sh[i] = 0;
    __syncthreads();
    int b = blockIdx.y;
    int base = blockIdx.x * (NA / NPART);
    #pragma unroll
    for (int k = 0; k < (NA / NPART) / NTHR; k++) {
        int i = base + k * NTHR + threadIdx.x;
        float4 a = anchors[i];
        bool valid = (a.z <= 1.0f) && (a.w <= 1.0f) && (a.x >= 0.0f) && (a.y >= 0.0f);
        float s = score[(size_t)b * NA + i];
        float ms = valid ? s : -1.0f;
        atomicAdd(&sh[bucketOf(ms)], 1);
    }
    __syncthreads();
    for (int i = threadIdx.x; i < NBUCKET; i += NTHR)
        g_histpart[blockIdx.x][b][i] = sh[i];
}

// ---------------- kernel 2: per-batch threshold bucket (1 block per batch) ----------------
__global__ void k_findthr() {
    __shared__ int tot[NBUCKET];
    int b = blockIdx.x;
    for (int j = 0; j < NBUCKET / NTHR; j++) {
        int bucket = j * NTHR + threadIdx.x;
        int s = 0;
        #pragma unroll
        for (int p = 0; p < NPART; p++) s += g_histpart[p][b][bucket];
        tot[bucket] = s;
    }
    if (threadIdx.x == 0) g_candcnt[b] = 0;
    __syncthreads();
    if (threadIdx.x < 32) {
        int lane = threadIdx.x;
        int cum = 0;
        for (int c = NBUCKET / 32 - 1; c >= 0; --c) {
            int cnt = tot[c * 32 + lane];
            int s = cnt;
            #pragma unroll
            for (int off = 1; off < 32; off <<= 1) {
                int t = __shfl_down_sync(0xffffffffu, s, off);
                if (lane + off < 32) s += t;
            }
            int chunkSum = __shfl_sync(0xffffffffu, s, 0);
            if (cum + chunkSum >= KSEL) {
                bool pred = (cum + s) >= KSEL;
                unsigned bal = __ballot_sync(0xffffffffu, pred);
                int bl = 31 - __clz(bal);
                if (lane == 0) g_thr[b] = c * 32 + bl;
                return;
            }
            cum += chunkSum;
        }
        if (lane == 0) g_thr[b] = 0;
    }
}

// ---------------- kernel 3: compact candidates (bucket >= threshold) ----------------
__global__ void k_compact(const float* __restrict__ score,
                          const float4* __restrict__ anchors) {
    int b = blockIdx.y;
    int thr = g_thr[b];
    int base = blockIdx.x * (NA / 64);
    #pragma unroll
    for (int k = 0; k < (NA / 64) / 512; k++) {
        int i = base + k * 512 + threadIdx.x;
        float4 a = anchors[i];
        bool valid = (a.z <= 1.0f) && (a.w <= 1.0f) && (a.x >= 0.0f) && (a.y >= 0.0f);
        float s = score[(size_t)b * NA + i];
        float ms = valid ? s : -1.0f;
        if (bucketOf(ms) >= thr) {
            int p = atomicAdd(&g_candcnt[b], 1);
            if (p < SORTN) {
                g_candkey[b][p] =
                    ((unsigned long long)orderable(ms) << 32) | (unsigned)(NA - 1 - i);
            }
        }
    }
}

// ---------------- kernel 4: sort + decode + Morton sort + soft-NMS ----------------
extern __shared__ unsigned char smem_raw[];

__global__ void __launch_bounds__(NTHR, 1)
k_sortnms(const float4* __restrict__ regress,
          const float4* __restrict__ anchors,
          float4* __restrict__ out) {
    unsigned long long* keys = (unsigned long long*)smem_raw;            // 8192 u64
    float4* boxes  = (float4*)(smem_raw + (size_t)SORTN * 8);            // KPAD float4 (by rank)
    float*  scores = (float*) (smem_raw + (size_t)SORTN * 8 + (size_t)KPAD * 16); // KPAD f32
    __shared__ unsigned long long s_wmax[32];
    __shared__ unsigned long long s_best;

    int b = blockIdx.x;
    int tid = threadIdx.x;
    int lane = tid & 31;
    int wid = tid >> 5;

    // ---- load candidates, pad with 0 ----
    int cnt = g_candcnt[b];
    if (cnt > SORTN) cnt = SORTN;
    for (int i = tid; i < SORTN; i += NTHR)
        keys[i] = (i < cnt) ? g_candkey[b][i] : 0ULL;
    __syncthreads();

    // ---- bitonic sort #1: DESCENDING (score desc, orig idx asc) ----
    for (int k = 2; k <= SORTN; k <<= 1) {
        for (int j = k >> 1; j > 0; j >>= 1) {
            for (int i = tid; i < SORTN; i += NTHR) {
                int ixj = i ^ j;
                if (ixj > i) {
                    unsigned long long a = keys[i], c = keys[ixj];
                    bool sw = ((i & k) == 0) ? (a < c) : (a > c);
                    if (sw) { keys[i] = c; keys[ixj] = a; }
                }
            }
            __syncthreads();
        }
    }

    // ---- decode ranks [0,KSEL): delta2bbox + clip (exact RN); build Morton keys ----
    const float MR = (float)4.135166556742356;   // abs(log(16/1000))
#pragma unroll
    for (int k = 0; k < 5; k++) {
        int slot = tid + k * NTHR;                // 0..5119, slot == rank
        unsigned long long mkey;
        if (slot < KSEL) {
            unsigned long long key = keys[slot];
            unsigned idx = (unsigned)(NA - 1) - (unsigned)(key & 0xFFFFFFFFull);
            float s = fromOrderable((unsigned)(key >> 32));
            float4 t = regress[(size_t)b * NA + idx];
            float4 a = anchors[idx];
            float d0 = __fadd_rn(__fmul_rn(t.x, 0.1f), 0.0f);
            float d1 = __fadd_rn(__fmul_rn(t.y, 0.1f), 0.0f);
            float d2 = __fadd_rn(__fmul_rn(t.z, 0.2f), 0.0f);
            float d3 = __fadd_rn(__fmul_rn(t.w, 0.2f), 0.0f);
            d2 = fminf(fmaxf(d2, -MR), MR);
            d3 = fminf(fmaxf(d3, -MR), MR);
            float awx = __fsub_rn(a.z, a.x), awy = __fsub_rn(a.w, a.y);
            float acx = __fmul_rn(__fadd_rn(a.z, a.x), 0.5f);
            float acy = __fmul_rn(__fadd_rn(a.w, a.y), 0.5f);
            float cx = __fadd_rn(acx, __fmul_rn(d0, awx));
            float cy = __fadd_rn(acy, __fmul_rn(d1, awy));
            float wx = __fmul_rn(awx, xla_expf(d2));
            float wy = __fmul_rn(awy, xla_expf(d3));
            float x1 = __fsub_rn(cx, __fmul_rn(wx, 0.5f));
            float y1 = __fsub_rn(cy, __fmul_rn(wy, 0.5f));
            float x2 = __fadd_rn(cx, __fmul_rn(wx, 0.5f));
            float y2 = __fadd_rn(cy, __fmul_rn(wy, 0.5f));
            x1 = fminf(fmaxf(x1, 0.f), 1.f);
            y1 = fminf(fmaxf(y1, 0.f), 1.f);
            x2 = fminf(fmaxf(x2, 0.f), 1.f);
            y2 = fminf(fmaxf(y2, 0.f), 1.f);
            boxes[slot]  = make_float4(x1, y1, x2, y2);
            scores[slot] = s;
            // Morton of center (perf only, no exactness requirement)
            float mcx = (x1 + x2) * 0.5f, mcy = (y1 + y2) * 0.5f;
            unsigned xb = (unsigned)fminf(fmaxf(mcx * 1024.0f, 0.0f), 1023.0f);
            unsigned yb = (unsigned)fminf(fmaxf(mcy * 1024.0f, 0.0f), 1023.0f);
            unsigned mort = (part1by1(yb) << 1) | part1by1(xb);
            mkey = ((unsigned long long)mort << 13) | (unsigned)slot;
        } else {
            boxes[slot]  = make_float4(0.f, 0.f, 0.f, 0.f);
            scores[slot] = NEGV;
            mkey = (0xFFFFFULL << 13) | (unsigned)slot;   // dummies to the end
        }
        keys[slot] = mkey;    // safe: each slot touched by exactly one thread
    }
    for (int i = KPAD + tid; i < SORTN; i += NTHR) keys[i] = ~0ULL;
    __syncthreads();

    // ---- bitonic sort #2: ASCENDING by Morton (spatial clustering) ----
    for (int k = 2; k <= SORTN; k <<= 1) {
        for (int j = k >> 1; j > 0; j >>= 1) {
            for (int i = tid; i < SORTN; i += NTHR) {
                int ixj = i ^ j;
                if (ixj > i) {
                    unsigned long long a = keys[i], c = keys[ixj];
                    bool sw = ((i & k) == 0) ? (a > c) : (a < c);
                    if (sw) { keys[i] = c; keys[ixj] = a; }
                }
            }
            __syncthreads();
        }
    }

    // ---- take ownership: 5 CONTIGUOUS sorted slots; boxes into REGISTERS ----
    float msc[5];
    float4 bx[5];            // loop-resident element boxes (no per-iter gathers)
    unsigned lowk[5];        // SORTN-1-rank (key low field; pick match by equality)
    float wbx1 = 1e9f, wby1 = 1e9f, wbx2 = -1e9f, wby2 = -1e9f;
#pragma unroll
    for (int k = 0; k < 5; k++) {
        int p = tid * 5 + k;                       // < 5120
        int r = (int)(keys[p] & 0x1FFFULL);
        lowk[k] = (unsigned)(SORTN - 1 - r);
        msc[k] = scores[r];
        bx[k]  = boxes[r];
        if (r < KSEL) {
            wbx1 = fminf(wbx1, bx[k].x); wby1 = fminf(wby1, bx[k].y);
            wbx2 = fmaxf(wbx2, bx[k].z); wby2 = fmaxf(wby2, bx[k].w);
        }
    }
    // cached thread-max argmax key
    unsigned long long tkey = 0ULL;
#pragma unroll
    for (int k = 0; k < 5; k++) {
        unsigned long long kk = ((unsigned long long)orderable(msc[k]) << 32) | lowk[k];
        if (kk > tkey) tkey = kk;
    }
    // warp max -> s_wmax
    {
        unsigned long long v = tkey;
#pragma unroll
        for (int off = 16; off; off >>= 1) {
            unsigned long long o = __shfl_down_sync(0xffffffffu, v, off);
            if (o > v) v = o;
        }
        if (lane == 0) s_wmax[wid] = v;
    }
    // warp bbox (union of thread bboxes)
#pragma unroll
    for (int off = 16; off; off >>= 1) {
        wbx1 = fminf(wbx1, __shfl_xor_sync(0xffffffffu, wbx1, off));
        wby1 = fminf(wby1, __shfl_xor_sync(0xffffffffu, wby1, off));
        wbx2 = fmaxf(wbx2, __shfl_xor_sync(0xffffffffu, wbx2, off));
        wby2 = fmaxf(wby2, __shfl_xor_sync(0xffffffffu, wby2, off));
    }
    __syncthreads();

    // ---- soft-NMS: 1000 strictly sequential iterations ----
    for (int it = 0; it < NOUT; ++it) {
        // block argmax from cached per-warp maxima
        if (wid == 0) {
            unsigned long long v = s_wmax[lane];
#pragma unroll
            for (int off = 16; off; off >>= 1) {
                unsigned long long o = __shfl_down_sync(0xffffffffu, v, off);
                if (o > v) v = o;
            }
            if (lane == 0) s_best = v;
        }
        __syncthreads();

        unsigned long long bk = s_best;
        unsigned picklo = (unsigned)(bk & 0xFFFFFFFFull);
        int pickrank = (SORTN - 1) - (int)picklo;
        float ps = fromOrderable((unsigned)(bk >> 32));
        float4 pb = boxes[pickrank];               // broadcast LDS

        if (tid == 0)
            out[b * NOUT + it] = (ps > NEGV * 0.5f) ? pb : make_float4(0.f, 0.f, 0.f, 0.f);

        // warp-level spatial skip (exact: bbox-miss => inter==0 => factor==1.0)
        bool wact = (fminf(pb.z, wbx2) > fmaxf(pb.x, wbx1)) &&
                    (fminf(pb.w, wby2) > fmaxf(pb.y, wby1));
        if (wact) {
            float parea = __fmul_rn(__fsub_rn(pb.z, pb.x), __fsub_rn(pb.w, pb.y));
            bool changed = false;
#pragma unroll
            for (int k = 0; k < 5; k++) {
                float ltx = fmaxf(pb.x, bx[k].x), lty = fmaxf(pb.y, bx[k].y);
                float rbx = fminf(pb.z, bx[k].z), rby = fminf(pb.w, bx[k].w);
                float iw = fmaxf(__fsub_rn(rbx, ltx), 0.0f);
                float ih = fmaxf(__fsub_rn(rby, lty), 0.0f);
                float inter = __fmul_rn(iw, ih);
                if (inter > 0.0f) {
                    float barea = __fmul_rn(__fsub_rn(bx[k].z, bx[k].x),
                                            __fsub_rn(bx[k].w, bx[k].y));
                    float den = __fadd_rn(__fsub_rn(__fadd_rn(parea, barea), inter), 1e-12f);
                    float iou = __fdiv_rn(inter, den);
                    float arg = -__fmul_rn(iou, iou);   // == -0.5*iou*iou/0.5 exactly
                    msc[k] = __fmul_rn(msc[k], xla_expf(arg));
                    changed = true;
                }
                if (lowk[k] == picklo) { msc[k] = NEGV; changed = true; }
            }
            if (__ballot_sync(0xffffffffu, changed)) {
                if (changed) {
                    tkey = 0ULL;
#pragma unroll
                    for (int k = 0; k < 5; k++) {
                        unsigned long long kk =
                            ((unsigned long long)orderable(msc[k]) << 32) | lowk[k];
                        if (kk > tkey) tkey = kk;
                    }
                }
                unsigned long long v = tkey;
#pragma unroll
                for (int off = 16; off; off >>= 1) {
                    unsigned long long o = __shfl_down_sync(0xffffffffu, v, off);
                    if (o > v) v = o;
                }
                if (lane == 0) s_wmax[wid] = v;
            }
        }
        __syncthreads();
    }
}

// ---------------- launch ----------------
extern "C" void kernel_launch(void* const* d_in, const int* in_sizes, int n_in,
                              void* d_out, int out_size) {
    const float*  score   = (const float*)d_in[0];
    const float4* regress = (const float4*)d_in[1];
    const float4* anchors = (const float4*)d_in[2];
    float4* out = (float4*)d_out;

    const int smem_bytes = SORTN * 8 + KPAD * 16 + KPAD * 4;  // 167936
    cudaFuncSetAttribute(k_sortnms, cudaFuncAttributeMaxDynamicSharedMemorySize, smem_bytes);

    k_mask_hist<<<dim3(NPART, BATCH), NTHR>>>(score, anchors);
    k_findthr<<<BATCH, NTHR>>>();
    k_compact<<<dim3(64, BATCH), 512>>>(score, anchors);
    k_sortnms<<<BATCH, NTHR, smem_bytes>>>(regress, anchors, out);
}